// round 13
// baseline (speedup 1.0000x reference)
#include <cuda_runtime.h>
#include <cuda_bf16.h>
#include <math.h>
#include <stdint.h>

// Problem constants
#define BB 4
#define SS 4096
#define DD 512
#define MTOT (BB*SS)          // 16384 flattened rows

// Tiling
#define BM 128
#define BN 128
#define BK 32
#define NTHR 128              // 4 warps: 2 (M) x 2 (N), warp tile 64x64
#define STAGES 3

// smem: unpadded bf16 tiles 128 rows x 32 cols = 64B/row, XOR-swizzled chunks
#define TILE_B   (128 * 64)       // 8192 bytes
#define STAGE_B  (4 * TILE_B)     // Ahi, Alo, Bhi, Blo = 32768
#define SMEM_BYTES (STAGES * STAGE_B)  // 98304

// swizzled byte offset of 16B chunk (row, c), c = k-chunk 0..3
#define SWZ(row, c) ((uint32_t)((row) * 64 + ((((c) ^ (((row) >> 1) & 3))) << 4)))

// epilogue modes
#define MODE_BIAS_F32    0   // C_f32 = acc + bias      (final output)
#define MODE_TBIAS_SPLIT 1   // Ch/Cl = acc + bias, transposed [D][S] store (kvT)
#define MODE_PLAIN_F32   2   // C_f32 = acc             (attn logits)
#define MODE_RES_SPLIT   3   // Ch/Cl = acc + R         (o = AV + qv)
#define MODE_BIAS_SPLIT  4   // Ch/Cl = acc + bias      (q, k)

typedef __nv_bfloat16 bf16;

// -------- scratch (device globals: allocation-free rule) --------
__device__ bf16  g_xs_h[MTOT * DD], g_xs_l[MTOT * DD];
__device__ bf16  g_ys_h[MTOT * DD], g_ys_l[MTOT * DD];
__device__ bf16  g_Wq_h [DD * DD], g_Wq_l [DD * DD];
__device__ bf16  g_Wqv_h[DD * DD], g_Wqv_l[DD * DD];
__device__ bf16  g_Wk_h [DD * DD], g_Wk_l [DD * DD];
__device__ bf16  g_Wkv_h[DD * DD], g_Wkv_l[DD * DD];
__device__ bf16  g_Wf_h [DD * DD], g_Wf_l [DD * DD];
__device__ bf16  g_q_h [MTOT * DD], g_q_l [MTOT * DD];
__device__ bf16  g_k_h [MTOT * DD], g_k_l [MTOT * DD];
__device__ bf16  g_kvT_h[MTOT * DD], g_kvT_l[MTOT * DD];   // [B][D][S]
__device__ bf16  g_o_h [MTOT * DD], g_o_l [MTOT * DD];
__device__ float g_qv [MTOT * DD];
__device__ float g_attn[(size_t)BB * SS * SS];             // 256 MB logits
__device__ bf16  g_attn_h[(size_t)BB * SS * SS];           // 128 MB
__device__ bf16  g_attn_l[(size_t)BB * SS * SS];           // 128 MB

__device__ __forceinline__ uint32_t smem_u32(const void* p) {
    uint32_t a;
    asm("{ .reg .u64 t; cvta.to.shared.u64 t, %1; cvt.u32.u64 %0, t; }"
        : "=r"(a) : "l"(p));
    return a;
}

__device__ __forceinline__ void mma_bf16(float c[4],
                                         uint32_t a0, uint32_t a1, uint32_t a2, uint32_t a3,
                                         uint32_t b0, uint32_t b1) {
    asm volatile(
        "mma.sync.aligned.m16n8k16.row.col.f32.bf16.bf16.f32 "
        "{%0,%1,%2,%3}, {%4,%5,%6,%7}, {%8,%9}, {%0,%1,%2,%3};\n"
        : "+f"(c[0]), "+f"(c[1]), "+f"(c[2]), "+f"(c[3])
        : "r"(a0), "r"(a1), "r"(a2), "r"(a3), "r"(b0), "r"(b1));
}

__device__ __forceinline__ void ldsm4(uint32_t& r0, uint32_t& r1, uint32_t& r2, uint32_t& r3,
                                      uint32_t addr) {
    asm volatile("ldmatrix.sync.aligned.m8n8.x4.shared.b16 {%0,%1,%2,%3}, [%4];"
                 : "=r"(r0), "=r"(r1), "=r"(r2), "=r"(r3) : "r"(addr));
}

#define CP16(sp, gp) \
    asm volatile("cp.async.cg.shared.global [%0], [%1], 16;" :: "r"(sp), "l"(gp))
#define CP_COMMIT() asm volatile("cp.async.commit_group;" ::: "memory")
#define CP_WAIT2()  asm volatile("cp.async.wait_group 2;" ::: "memory")

// split float pair -> hi bf162 word + lo bf162 word
__device__ __forceinline__ void split2(float a, float b, uint32_t& h, uint32_t& l) {
    __nv_bfloat162 hh, ll;
    hh.x = __float2bfloat16_rn(a);
    hh.y = __float2bfloat16_rn(b);
    ll.x = __float2bfloat16_rn(a - __bfloat162float(hh.x));
    ll.y = __float2bfloat16_rn(b - __bfloat162float(hh.y));
    h = *(uint32_t*)&hh;
    l = *(uint32_t*)&ll;
}

// ============================================================
// presplit: fp32 -> bf16 hi + bf16 lo, elementwise
// ============================================================
__global__ __launch_bounds__(256)
void presplit(const float* __restrict__ in, bf16* __restrict__ hi,
              bf16* __restrict__ lo, int n)
{
    const int i = (blockIdx.x * 256 + threadIdx.x) * 4;
    if (i >= n) return;
    float4 v = *(const float4*)(in + i);
    uint32_t h0, l0, h1, l1;
    split2(v.x, v.y, h0, l0);
    split2(v.z, v.w, h1, l1);
    uint2 hh = make_uint2(h0, h1), ll = make_uint2(l0, l1);
    *(uint2*)(hi + i) = hh;
    *(uint2*)(lo + i) = ll;
}

// ============================================================
// NT bf16x3 GEMM: 128-thread CTA, 64x64 warp tiles, cp.async.
// C[M,N] = A[M,K] * B[N,K]^T, inputs pre-split hi/lo bf16.
// Batched via blockIdx.z. M,N %128==0, K %32==0.
// ============================================================
template <int MODE>
__global__ __launch_bounds__(NTHR, 2)
void cp_nt3(const bf16* __restrict__ Ah, const bf16* __restrict__ Al,
            const bf16* __restrict__ Bh, const bf16* __restrict__ Bl,
            const float* __restrict__ aux,      // bias or residual R
            float* __restrict__ C, bf16* __restrict__ Ch, bf16* __restrict__ Cl,
            int M, int N, int K,
            long sA, long sB, long sAux, long sC)
{
    extern __shared__ __align__(128) char smem[];
    const uint32_t sbase = smem_u32(smem);

    const int bz = blockIdx.z;
    Ah += (long)bz * sA;  Al += (long)bz * sA;
    Bh += (long)bz * sB;  Bl += (long)bz * sB;
    const float* R = aux ? aux + (long)bz * sAux : (const float*)0;
    if (C)  C  += (long)bz * sC;
    if (Ch) { Ch += (long)bz * sC; Cl += (long)bz * sC; }

    const int m0 = blockIdx.y * BM;
    const int n0 = blockIdx.x * BN;
    const int tid  = threadIdx.x;
    const int wid  = tid >> 5;
    const int lane = tid & 31;
    const int g = lane >> 2;       // 0..7
    const int t = lane & 3;        // 0..3
    const int warp_m = wid & 1;    // 0..1 -> 64 rows
    const int warp_n = wid >> 1;   // 0..1 -> 64 cols

    // ldmatrix lane roles
    const int quad = lane >> 3;
    const int lr8  = lane & 7;
    const int rq   = (quad & 1) * 8 + lr8;
    const int cq   = quad >> 1;

    // loader roles: per tile, 4 iterations: row = (tid>>2)+i*32, chunk = tid&3
    const int lrow  = tid >> 2;      // 0..31
    const int lchnk = tid & 3;
    const bf16* tb[4] = { Ah + (long)m0 * K, Al + (long)m0 * K,
                          Bh + (long)n0 * K, Bl + (long)n0 * K };

    float acc[4][8][4];
    #pragma unroll
    for (int mf = 0; mf < 4; mf++)
        #pragma unroll
        for (int nf = 0; nf < 8; nf++)
            #pragma unroll
            for (int r = 0; r < 4; r++) acc[mf][nf][r] = 0.f;

    const int KT = K / BK;

    #define ISSUE_STAGE(kt_, s_) do {                                          \
        const int k0_ = (kt_) * BK;                                            \
        _Pragma("unroll")                                                      \
        for (int tile_ = 0; tile_ < 4; tile_++) {                              \
            _Pragma("unroll")                                                  \
            for (int i_ = 0; i_ < 4; i_++) {                                   \
                const int row_ = lrow + i_ * 32;                               \
                const bf16* gp_ = tb[tile_] + (long)row_ * K + k0_ + lchnk * 8;\
                uint32_t sp_ = sbase + (s_) * STAGE_B + tile_ * TILE_B         \
                             + SWZ(row_, lchnk);                               \
                CP16(sp_, gp_);                                                \
            }                                                                  \
        }                                                                      \
    } while (0)

    ISSUE_STAGE(0, 0); CP_COMMIT();
    ISSUE_STAGE(1, 1); CP_COMMIT();

    for (int kt = 0; kt < KT; kt++) {
        if (kt + 2 < KT) ISSUE_STAGE(kt + 2, (kt + 2) % STAGES);
        CP_COMMIT();                 // always commit (empty group on tail)
        CP_WAIT2();
        __syncthreads();

        const uint32_t stg = sbase + (kt % STAGES) * STAGE_B;
        const uint32_t aHiB = stg;
        const uint32_t aLoB = stg + TILE_B;
        const uint32_t bHiB = stg + 2 * TILE_B;
        const uint32_t bLoB = stg + 3 * TILE_B;

        #pragma unroll
        for (int ks = 0; ks < 2; ks++) {
            const int ck = ks * 2 + cq;
            uint32_t ah[4][4], al[4][4], bh[8][2], bl[8][2];
            #pragma unroll
            for (int mf = 0; mf < 4; mf++) {
                const int row = warp_m * 64 + mf * 16 + rq;
                const uint32_t off = SWZ(row, ck);
                ldsm4(ah[mf][0], ah[mf][1], ah[mf][2], ah[mf][3], aHiB + off);
                ldsm4(al[mf][0], al[mf][1], al[mf][2], al[mf][3], aLoB + off);
            }
            #pragma unroll
            for (int p = 0; p < 4; p++) {
                const int row = warp_n * 64 + p * 16 + rq;
                const uint32_t off = SWZ(row, ck);
                uint32_t q0, q1, q2, q3;
                ldsm4(q0, q1, q2, q3, bHiB + off);
                bh[2*p][0] = q0; bh[2*p+1][0] = q1;
                bh[2*p][1] = q2; bh[2*p+1][1] = q3;
                ldsm4(q0, q1, q2, q3, bLoB + off);
                bl[2*p][0] = q0; bl[2*p+1][0] = q1;
                bl[2*p][1] = q2; bl[2*p+1][1] = q3;
            }
            #pragma unroll
            for (int mf = 0; mf < 4; mf++)
                #pragma unroll
                for (int nf = 0; nf < 8; nf++) {
                    mma_bf16(acc[mf][nf], ah[mf][0], ah[mf][1], ah[mf][2], ah[mf][3],
                             bh[nf][0], bh[nf][1]);
                    mma_bf16(acc[mf][nf], ah[mf][0], ah[mf][1], ah[mf][2], ah[mf][3],
                             bl[nf][0], bl[nf][1]);
                    mma_bf16(acc[mf][nf], al[mf][0], al[mf][1], al[mf][2], al[mf][3],
                             bh[nf][0], bh[nf][1]);
                }
        }
        __syncthreads();
    }

    // ---------------- epilogue ----------------
    if (MODE == MODE_TBIAS_SPLIT) {
        const long cbase = (long)(m0 >> 12) * DD * SS;
        const int  s0    = (m0 & (SS - 1)) + warp_m * 64;
        #pragma unroll
        for (int nf = 0; nf < 8; nf++) {
            const int col = warp_n * 64 + nf * 8 + t * 2;
            const float b0 = aux[n0 + col];
            const float b1 = aux[n0 + col + 1];
            #pragma unroll
            for (int mf = 0; mf < 4; mf++) {
                const int srow = s0 + mf * 16 + g;
                const long i00 = cbase + (long)(n0 + col) * SS + srow;
                const long i01 = cbase + (long)(n0 + col + 1) * SS + srow;
                float v00 = acc[mf][nf][0] + b0, v01 = acc[mf][nf][1] + b1;
                float v10 = acc[mf][nf][2] + b0, v11 = acc[mf][nf][3] + b1;
                bf16 h;
                h = __float2bfloat16_rn(v00); Ch[i00]     = h; Cl[i00]     = __float2bfloat16_rn(v00 - __bfloat162float(h));
                h = __float2bfloat16_rn(v01); Ch[i01]     = h; Cl[i01]     = __float2bfloat16_rn(v01 - __bfloat162float(h));
                h = __float2bfloat16_rn(v10); Ch[i00 + 8] = h; Cl[i00 + 8] = __float2bfloat16_rn(v10 - __bfloat162float(h));
                h = __float2bfloat16_rn(v11); Ch[i01 + 8] = h; Cl[i01 + 8] = __float2bfloat16_rn(v11 - __bfloat162float(h));
            }
        }
    } else {
        #pragma unroll
        for (int nf = 0; nf < 8; nf++) {
            const int col = n0 + warp_n * 64 + nf * 8 + t * 2;
            float b0 = 0.f, b1 = 0.f;
            if (MODE == MODE_BIAS_F32 || MODE == MODE_BIAS_SPLIT) {
                b0 = aux[col]; b1 = aux[col + 1];
            }
            #pragma unroll
            for (int mf = 0; mf < 4; mf++) {
                const int row0 = m0 + warp_m * 64 + mf * 16 + g;
                float r00 = b0, r01 = b1, r10 = b0, r11 = b1;
                if (MODE == MODE_RES_SPLIT) {
                    float2 rr0 = *(const float2*)(R + (long)row0 * N + col);
                    float2 rr1 = *(const float2*)(R + (long)(row0 + 8) * N + col);
                    r00 = rr0.x; r01 = rr0.y; r10 = rr1.x; r11 = rr1.y;
                }
                const float v00 = acc[mf][nf][0] + r00;
                const float v01 = acc[mf][nf][1] + r01;
                const float v10 = acc[mf][nf][2] + r10;
                const float v11 = acc[mf][nf][3] + r11;
                if (MODE == MODE_BIAS_F32 || MODE == MODE_PLAIN_F32) {
                    *(float2*)(C + (long)row0 * N + col)       = make_float2(v00, v01);
                    *(float2*)(C + (long)(row0 + 8) * N + col) = make_float2(v10, v11);
                } else {
                    uint32_t h0, l0, h1, l1;
                    split2(v00, v01, h0, l0);
                    split2(v10, v11, h1, l1);
                    *(uint32_t*)(Ch + (long)row0 * N + col)       = h0;
                    *(uint32_t*)(Cl + (long)row0 * N + col)       = l0;
                    *(uint32_t*)(Ch + (long)(row0 + 8) * N + col) = h1;
                    *(uint32_t*)(Cl + (long)(row0 + 8) * N + col) = l1;
                }
            }
        }
    }
}

// ============================================================
// Row softmax over SS=4096 columns -> bf16 hi/lo output.
// One block (256 thr) per row.
// ============================================================
__global__ __launch_bounds__(256)
void softmax_split(const float* __restrict__ attn,
                   bf16* __restrict__ ph, bf16* __restrict__ pl)
{
    const size_t rb = (size_t)blockIdx.x * SS;
    const float* p = attn + rb;
    const int tid = threadIdx.x;

    float4 v[4];
    float mx = -INFINITY;
    #pragma unroll
    for (int i = 0; i < 4; i++) {
        v[i] = *(const float4*)(p + (tid + i * 256) * 4);
        mx = fmaxf(fmaxf(fmaxf(v[i].x, v[i].y), fmaxf(v[i].z, v[i].w)), mx);
    }
    __shared__ float red[8];
    #pragma unroll
    for (int o = 16; o; o >>= 1) mx = fmaxf(mx, __shfl_xor_sync(0xffffffffu, mx, o));
    if ((tid & 31) == 0) red[tid >> 5] = mx;
    __syncthreads();
    float m = red[0];
    #pragma unroll
    for (int i = 1; i < 8; i++) m = fmaxf(m, red[i]);
    __syncthreads();

    float s = 0.f;
    #pragma unroll
    for (int i = 0; i < 4; i++) {
        v[i].x = __expf(v[i].x - m); v[i].y = __expf(v[i].y - m);
        v[i].z = __expf(v[i].z - m); v[i].w = __expf(v[i].w - m);
        s += v[i].x + v[i].y + v[i].z + v[i].w;
    }
    #pragma unroll
    for (int o = 16; o; o >>= 1) s += __shfl_xor_sync(0xffffffffu, s, o);
    if ((tid & 31) == 0) red[tid >> 5] = s;
    __syncthreads();
    float tot = 0.f;
    #pragma unroll
    for (int i = 0; i < 8; i++) tot += red[i];
    const float inv = 1.f / tot;

    #pragma unroll
    for (int i = 0; i < 4; i++) {
        const float p0 = v[i].x * inv, p1 = v[i].y * inv;
        const float p2 = v[i].z * inv, p3 = v[i].w * inv;
        uint32_t h0, l0, h1, l1;
        split2(p0, p1, h0, l0);
        split2(p2, p3, h1, l1);
        const size_t idx = rb + (size_t)(tid + i * 256) * 4;
        *(uint2*)(ph + idx) = make_uint2(h0, h1);
        *(uint2*)(pl + idx) = make_uint2(l0, l1);
    }
}

// ============================================================
extern "C" void kernel_launch(void* const* d_in, const int* in_sizes, int n_in,
                              void* d_out, int out_size)
{
    const float* x   = (const float*)d_in[0];
    const float* y   = (const float*)d_in[1];
    const float* Wq  = (const float*)d_in[2];
    const float* bq  = (const float*)d_in[3];
    const float* Wqv = (const float*)d_in[4];
    const float* bqv = (const float*)d_in[5];
    const float* Wk  = (const float*)d_in[6];
    const float* bk  = (const float*)d_in[7];
    const float* Wkv = (const float*)d_in[8];
    const float* bkv = (const float*)d_in[9];
    const float* Wf  = (const float*)d_in[10];
    const float* bf  = (const float*)d_in[11];
    float* out = (float*)d_out;

    bf16 *xs_h, *xs_l, *ys_h, *ys_l;
    bf16 *Wq_h, *Wq_l, *Wqv_h, *Wqv_l, *Wk_h, *Wk_l, *Wkv_h, *Wkv_l, *Wf_h, *Wf_l;
    bf16 *q_h, *q_l, *k_h, *k_l, *kvT_h, *kvT_l, *o_h, *o_l, *at_h, *at_l;
    float *qv, *attn;
    cudaGetSymbolAddress((void**)&xs_h,  g_xs_h);  cudaGetSymbolAddress((void**)&xs_l,  g_xs_l);
    cudaGetSymbolAddress((void**)&ys_h,  g_ys_h);  cudaGetSymbolAddress((void**)&ys_l,  g_ys_l);
    cudaGetSymbolAddress((void**)&Wq_h,  g_Wq_h);  cudaGetSymbolAddress((void**)&Wq_l,  g_Wq_l);
    cudaGetSymbolAddress((void**)&Wqv_h, g_Wqv_h); cudaGetSymbolAddress((void**)&Wqv_l, g_Wqv_l);
    cudaGetSymbolAddress((void**)&Wk_h,  g_Wk_h);  cudaGetSymbolAddress((void**)&Wk_l,  g_Wk_l);
    cudaGetSymbolAddress((void**)&Wkv_h, g_Wkv_h); cudaGetSymbolAddress((void**)&Wkv_l, g_Wkv_l);
    cudaGetSymbolAddress((void**)&Wf_h,  g_Wf_h);  cudaGetSymbolAddress((void**)&Wf_l,  g_Wf_l);
    cudaGetSymbolAddress((void**)&q_h,   g_q_h);   cudaGetSymbolAddress((void**)&q_l,   g_q_l);
    cudaGetSymbolAddress((void**)&k_h,   g_k_h);   cudaGetSymbolAddress((void**)&k_l,   g_k_l);
    cudaGetSymbolAddress((void**)&kvT_h, g_kvT_h); cudaGetSymbolAddress((void**)&kvT_l, g_kvT_l);
    cudaGetSymbolAddress((void**)&o_h,   g_o_h);   cudaGetSymbolAddress((void**)&o_l,   g_o_l);
    cudaGetSymbolAddress((void**)&at_h,  g_attn_h);cudaGetSymbolAddress((void**)&at_l,  g_attn_l);
    cudaGetSymbolAddress((void**)&qv,    g_qv);
    cudaGetSymbolAddress((void**)&attn,  g_attn);

    cudaFuncSetAttribute(cp_nt3<MODE_BIAS_F32>,    cudaFuncAttributeMaxDynamicSharedMemorySize, SMEM_BYTES);
    cudaFuncSetAttribute(cp_nt3<MODE_TBIAS_SPLIT>, cudaFuncAttributeMaxDynamicSharedMemorySize, SMEM_BYTES);
    cudaFuncSetAttribute(cp_nt3<MODE_PLAIN_F32>,   cudaFuncAttributeMaxDynamicSharedMemorySize, SMEM_BYTES);
    cudaFuncSetAttribute(cp_nt3<MODE_RES_SPLIT>,   cudaFuncAttributeMaxDynamicSharedMemorySize, SMEM_BYTES);
    cudaFuncSetAttribute(cp_nt3<MODE_BIAS_SPLIT>,  cudaFuncAttributeMaxDynamicSharedMemorySize, SMEM_BYTES);

    dim3 thr(NTHR);

    // 0. presplit inputs and weights to bf16 hi/lo
    presplit<<<MTOT * DD / 1024, 256>>>(x, xs_h, xs_l, MTOT * DD);
    presplit<<<MTOT * DD / 1024, 256>>>(y, ys_h, ys_l, MTOT * DD);
    presplit<<<DD * DD / 1024, 256>>>(Wq,  Wq_h,  Wq_l,  DD * DD);
    presplit<<<DD * DD / 1024, 256>>>(Wqv, Wqv_h, Wqv_l, DD * DD);
    presplit<<<DD * DD / 1024, 256>>>(Wk,  Wk_h,  Wk_l,  DD * DD);
    presplit<<<DD * DD / 1024, 256>>>(Wkv, Wkv_h, Wkv_l, DD * DD);
    presplit<<<DD * DD / 1024, 256>>>(Wf,  Wf_h,  Wf_l,  DD * DD);

    // 1-4. projections
    {
        dim3 grid(DD / BN, MTOT / BM, 1);
        cp_nt3<MODE_BIAS_SPLIT> <<<grid, thr, SMEM_BYTES>>>(xs_h, xs_l, Wq_h,  Wq_l,  bq,  nullptr, q_h, q_l,
                                                            MTOT, DD, DD, 0, 0, 0, 0);
        cp_nt3<MODE_BIAS_F32>   <<<grid, thr, SMEM_BYTES>>>(xs_h, xs_l, Wqv_h, Wqv_l, bqv, qv, nullptr, nullptr,
                                                            MTOT, DD, DD, 0, 0, 0, 0);
        cp_nt3<MODE_BIAS_SPLIT> <<<grid, thr, SMEM_BYTES>>>(ys_h, ys_l, Wk_h,  Wk_l,  bk,  nullptr, k_h, k_l,
                                                            MTOT, DD, DD, 0, 0, 0, 0);
        cp_nt3<MODE_TBIAS_SPLIT><<<grid, thr, SMEM_BYTES>>>(ys_h, ys_l, Wkv_h, Wkv_l, bkv, nullptr, kvT_h, kvT_l,
                                                            MTOT, DD, DD, 0, 0, 0, 0);
    }

    // 5. scores = q @ k^T per batch: [4096,4096], K=512
    {
        dim3 grid(SS / BN, SS / BM, BB);
        cp_nt3<MODE_PLAIN_F32><<<grid, thr, SMEM_BYTES>>>(q_h, q_l, k_h, k_l, nullptr, attn, nullptr, nullptr,
                                                          SS, SS, DD,
                                                          (long)SS * DD, (long)SS * DD, 0, (long)SS * SS);
    }

    // 6. softmax -> bf16 hi/lo probabilities
    softmax_split<<<BB * SS, 256>>>(attn, at_h, at_l);

    // 7. o = attn @ kvT^T + qv per batch: [4096,512], K=4096 (NT form)
    {
        dim3 grid(DD / BN, SS / BM, BB);
        cp_nt3<MODE_RES_SPLIT><<<grid, thr, SMEM_BYTES>>>(at_h, at_l, kvT_h, kvT_l, qv, nullptr, o_h, o_l,
                                                          SS, DD, SS,
                                                          (long)SS * SS, (long)DD * SS,
                                                          (long)SS * DD, (long)SS * DD);
    }

    // 8. final = o @ Wf^T + bf: [16384,512]
    {
        dim3 grid(DD / BN, MTOT / BM, 1);
        cp_nt3<MODE_BIAS_F32><<<grid, thr, SMEM_BYTES>>>(o_h, o_l, Wf_h, Wf_l, bf, out, nullptr, nullptr,
                                                         MTOT, DD, DD, 0, 0, 0, 0);
    }
}

// round 14
// speedup vs baseline: 1.0368x; 1.0368x over previous
#include <cuda_runtime.h>
#include <cuda_bf16.h>
#include <math.h>
#include <stdint.h>

// Problem constants
#define BB 4
#define SS 4096
#define DD 512
#define MTOT (BB*SS)          // 16384 flattened rows

// Tiling
#define BM 128
#define BN 128
#define BK 32
#define NTHR 256              // 8 warps: 2 (M) x 4 (N), warp tile 64x32
#define STAGES 3

// smem: unpadded bf16 tiles 128 rows x 32 cols = 64B/row, XOR-swizzled chunks
#define TILE_B   (128 * 64)       // 8192 bytes
#define STAGE_B  (4 * TILE_B)     // Ahi, Alo, Bhi, Blo = 32768
#define SMEM_BYTES (STAGES * STAGE_B)  // 98304

// swizzled byte offset of 16B chunk (row, c), c = k-chunk 0..3
#define SWZ(row, c) ((uint32_t)((row) * 64 + ((((c) ^ (((row) >> 1) & 3))) << 4)))

// epilogue modes
#define MODE_BIAS_F32    0   // C_f32 = acc + bias      (final output)
#define MODE_TBIAS_SPLIT 1   // Ch/Cl = acc + bias, transposed [D][S] store (kvT)
#define MODE_PLAIN_F32   2   // C_f32 = acc             (attn logits)
#define MODE_RES_SPLIT   3   // Ch/Cl = acc + R         (o = AV + qv)
#define MODE_BIAS_SPLIT  4   // Ch/Cl = acc + bias      (q, k)

typedef __nv_bfloat16 bf16;

// -------- scratch (device globals: allocation-free rule) --------
__device__ bf16  g_xs_h[MTOT * DD], g_xs_l[MTOT * DD];
__device__ bf16  g_ys_h[MTOT * DD], g_ys_l[MTOT * DD];
__device__ bf16  g_Wq_h [DD * DD], g_Wq_l [DD * DD];
__device__ bf16  g_Wqv_h[DD * DD], g_Wqv_l[DD * DD];
__device__ bf16  g_Wk_h [DD * DD], g_Wk_l [DD * DD];
__device__ bf16  g_Wkv_h[DD * DD], g_Wkv_l[DD * DD];
__device__ bf16  g_Wf_h [DD * DD], g_Wf_l [DD * DD];
__device__ bf16  g_q_h [MTOT * DD], g_q_l [MTOT * DD];
__device__ bf16  g_k_h [MTOT * DD], g_k_l [MTOT * DD];
__device__ bf16  g_kvT_h[MTOT * DD], g_kvT_l[MTOT * DD];   // [B][D][S]
__device__ bf16  g_o_h [MTOT * DD], g_o_l [MTOT * DD];
__device__ float g_qv [MTOT * DD];
__device__ float g_attn[(size_t)BB * SS * SS];             // 256 MB logits
__device__ bf16  g_attn_h[(size_t)BB * SS * SS];           // 128 MB
__device__ bf16  g_attn_l[(size_t)BB * SS * SS];           // 128 MB

__device__ __forceinline__ uint32_t smem_u32(const void* p) {
    uint32_t a;
    asm("{ .reg .u64 t; cvta.to.shared.u64 t, %1; cvt.u32.u64 %0, t; }"
        : "=r"(a) : "l"(p));
    return a;
}

__device__ __forceinline__ void mma_bf16(float c[4],
                                         uint32_t a0, uint32_t a1, uint32_t a2, uint32_t a3,
                                         uint32_t b0, uint32_t b1) {
    asm volatile(
        "mma.sync.aligned.m16n8k16.row.col.f32.bf16.bf16.f32 "
        "{%0,%1,%2,%3}, {%4,%5,%6,%7}, {%8,%9}, {%0,%1,%2,%3};\n"
        : "+f"(c[0]), "+f"(c[1]), "+f"(c[2]), "+f"(c[3])
        : "r"(a0), "r"(a1), "r"(a2), "r"(a3), "r"(b0), "r"(b1));
}

__device__ __forceinline__ void ldsm4(uint32_t& r0, uint32_t& r1, uint32_t& r2, uint32_t& r3,
                                      uint32_t addr) {
    asm volatile("ldmatrix.sync.aligned.m8n8.x4.shared.b16 {%0,%1,%2,%3}, [%4];"
                 : "=r"(r0), "=r"(r1), "=r"(r2), "=r"(r3) : "r"(addr));
}

#define CP16(sp, gp) \
    asm volatile("cp.async.cg.shared.global [%0], [%1], 16;" :: "r"(sp), "l"(gp))
#define CP_COMMIT() asm volatile("cp.async.commit_group;" ::: "memory")
#define CP_WAIT1()  asm volatile("cp.async.wait_group 1;" ::: "memory")

// split float pair -> hi bf162 word + lo bf162 word
__device__ __forceinline__ void split2(float a, float b, uint32_t& h, uint32_t& l) {
    __nv_bfloat162 hh, ll;
    hh.x = __float2bfloat16_rn(a);
    hh.y = __float2bfloat16_rn(b);
    ll.x = __float2bfloat16_rn(a - __bfloat162float(hh.x));
    ll.y = __float2bfloat16_rn(b - __bfloat162float(hh.y));
    h = *(uint32_t*)&hh;
    l = *(uint32_t*)&ll;
}

// ============================================================
// presplit: fp32 -> bf16 hi + bf16 lo, elementwise
// ============================================================
__global__ __launch_bounds__(256)
void presplit(const float* __restrict__ in, bf16* __restrict__ hi,
              bf16* __restrict__ lo, int n)
{
    const int i = (blockIdx.x * 256 + threadIdx.x) * 4;
    if (i >= n) return;
    float4 v = *(const float4*)(in + i);
    uint32_t h0, l0, h1, l1;
    split2(v.x, v.y, h0, l0);
    split2(v.z, v.w, h1, l1);
    uint2 hh = make_uint2(h0, h1), ll = make_uint2(l0, l1);
    *(uint2*)(hi + i) = hh;
    *(uint2*)(lo + i) = ll;
}

// ============================================================
// NT bf16x3 GEMM, cp.async pipeline (1 barrier/k-tile),
// term-major mma ordering. C[M,N] = A[M,K] * B[N,K]^T.
// Batched via blockIdx.z. M,N %128==0, K %32==0.
// ============================================================
template <int MODE>
__global__ __launch_bounds__(NTHR, 2)
void cp_nt3(const bf16* __restrict__ Ah, const bf16* __restrict__ Al,
            const bf16* __restrict__ Bh, const bf16* __restrict__ Bl,
            const float* __restrict__ aux,      // bias or residual R
            float* __restrict__ C, bf16* __restrict__ Ch, bf16* __restrict__ Cl,
            int M, int N, int K,
            long sA, long sB, long sAux, long sC)
{
    extern __shared__ __align__(128) char smem[];
    const uint32_t sbase = smem_u32(smem);

    const int bz = blockIdx.z;
    Ah += (long)bz * sA;  Al += (long)bz * sA;
    Bh += (long)bz * sB;  Bl += (long)bz * sB;
    const float* R = aux ? aux + (long)bz * sAux : (const float*)0;
    if (C)  C  += (long)bz * sC;
    if (Ch) { Ch += (long)bz * sC; Cl += (long)bz * sC; }

    const int m0 = blockIdx.y * BM;
    const int n0 = blockIdx.x * BN;
    const int tid  = threadIdx.x;
    const int wid  = tid >> 5;
    const int lane = tid & 31;
    const int g = lane >> 2;       // 0..7
    const int t = lane & 3;        // 0..3
    const int warp_m = wid & 1;    // 0..1
    const int warp_n = wid >> 1;   // 0..3

    // ldmatrix lane roles
    const int quad = lane >> 3;
    const int lr8  = lane & 7;
    const int rq   = (quad & 1) * 8 + lr8;
    const int cq   = quad >> 1;

    // loader roles: j 0..7 -> tile j>>1, row (tid>>2)+64*(j&1), chunk tid&3
    const int lrow  = tid >> 2;
    const int lchnk = tid & 3;
    const bf16* tb[4] = { Ah + (long)m0 * K, Al + (long)m0 * K,
                          Bh + (long)n0 * K, Bl + (long)n0 * K };

    float acc[4][4][4];
    #pragma unroll
    for (int mf = 0; mf < 4; mf++)
        #pragma unroll
        for (int nf = 0; nf < 4; nf++)
            #pragma unroll
            for (int r = 0; r < 4; r++) acc[mf][nf][r] = 0.f;

    const int KT = K / BK;

    #define ISSUE_STAGE(kt_, s_) do {                                          \
        const int k0_ = (kt_) * BK;                                            \
        _Pragma("unroll")                                                      \
        for (int j = 0; j < 8; j++) {                                          \
            const int tile_ = j >> 1;                                          \
            const int row_  = lrow + 64 * (j & 1);                             \
            const bf16* gp_ = tb[tile_] + (long)row_ * K + k0_ + lchnk * 8;    \
            uint32_t sp_ = sbase + (s_) * STAGE_B + tile_ * TILE_B             \
                         + SWZ(row_, lchnk);                                   \
            CP16(sp_, gp_);                                                    \
        }                                                                      \
    } while (0)

    ISSUE_STAGE(0, 0); CP_COMMIT();
    ISSUE_STAGE(1, 1); CP_COMMIT();

    for (int kt = 0; kt < KT; kt++) {
        // ensure stage kt%3 complete (<=1 newer group in flight)
        CP_WAIT1();
        __syncthreads();   // all warps see stage kt AND finished iter kt-1 reads

        // writing stage (kt+2)%3 == (kt-1)%3 is WAR-safe after the barrier
        if (kt + 2 < KT) ISSUE_STAGE(kt + 2, (kt + 2) % STAGES);
        CP_COMMIT();       // always commit (empty group on tail keeps count)

        const uint32_t stg = sbase + (kt % STAGES) * STAGE_B;
        const uint32_t aHiB = stg;
        const uint32_t aLoB = stg + TILE_B;
        const uint32_t bHiB = stg + 2 * TILE_B;
        const uint32_t bLoB = stg + 3 * TILE_B;

        #pragma unroll
        for (int ks = 0; ks < 2; ks++) {
            const int ck = ks * 2 + cq;
            uint32_t ah[4][4], al[4][4], bh[4][2], bl[4][2];
            #pragma unroll
            for (int mf = 0; mf < 4; mf++) {
                const int row = warp_m * 64 + mf * 16 + rq;
                const uint32_t off = SWZ(row, ck);
                ldsm4(ah[mf][0], ah[mf][1], ah[mf][2], ah[mf][3], aHiB + off);
                ldsm4(al[mf][0], al[mf][1], al[mf][2], al[mf][3], aLoB + off);
            }
            #pragma unroll
            for (int p = 0; p < 2; p++) {
                const int row = warp_n * 32 + p * 16 + rq;
                const uint32_t off = SWZ(row, ck);
                uint32_t q0, q1, q2, q3;
                ldsm4(q0, q1, q2, q3, bHiB + off);
                bh[2*p][0] = q0; bh[2*p+1][0] = q1;
                bh[2*p][1] = q2; bh[2*p+1][1] = q3;
                ldsm4(q0, q1, q2, q3, bLoB + off);
                bl[2*p][0] = q0; bl[2*p+1][0] = q1;
                bl[2*p][1] = q2; bl[2*p+1][1] = q3;
            }
            // term-major ordering: same-acc mmas are 16 instructions apart
            #pragma unroll
            for (int mf = 0; mf < 4; mf++)
                #pragma unroll
                for (int nf = 0; nf < 4; nf++)
                    mma_bf16(acc[mf][nf], ah[mf][0], ah[mf][1], ah[mf][2], ah[mf][3],
                             bh[nf][0], bh[nf][1]);
            #pragma unroll
            for (int mf = 0; mf < 4; mf++)
                #pragma unroll
                for (int nf = 0; nf < 4; nf++)
                    mma_bf16(acc[mf][nf], ah[mf][0], ah[mf][1], ah[mf][2], ah[mf][3],
                             bl[nf][0], bl[nf][1]);
            #pragma unroll
            for (int mf = 0; mf < 4; mf++)
                #pragma unroll
                for (int nf = 0; nf < 4; nf++)
                    mma_bf16(acc[mf][nf], al[mf][0], al[mf][1], al[mf][2], al[mf][3],
                             bh[nf][0], bh[nf][1]);
        }
    }

    // ---------------- epilogue ----------------
    if (MODE == MODE_TBIAS_SPLIT) {
        const long cbase = (long)(m0 >> 12) * DD * SS;
        const int  s0    = (m0 & (SS - 1)) + warp_m * 64;
        #pragma unroll
        for (int nf = 0; nf < 4; nf++) {
            const int col = warp_n * 32 + nf * 8 + t * 2;
            const float b0 = aux[n0 + col];
            const float b1 = aux[n0 + col + 1];
            #pragma unroll
            for (int mf = 0; mf < 4; mf++) {
                const int srow = s0 + mf * 16 + g;
                const long i00 = cbase + (long)(n0 + col) * SS + srow;
                const long i01 = cbase + (long)(n0 + col + 1) * SS + srow;
                float v00 = acc[mf][nf][0] + b0, v01 = acc[mf][nf][1] + b1;
                float v10 = acc[mf][nf][2] + b0, v11 = acc[mf][nf][3] + b1;
                bf16 h;
                h = __float2bfloat16_rn(v00); Ch[i00]     = h; Cl[i00]     = __float2bfloat16_rn(v00 - __bfloat162float(h));
                h = __float2bfloat16_rn(v01); Ch[i01]     = h; Cl[i01]     = __float2bfloat16_rn(v01 - __bfloat162float(h));
                h = __float2bfloat16_rn(v10); Ch[i00 + 8] = h; Cl[i00 + 8] = __float2bfloat16_rn(v10 - __bfloat162float(h));
                h = __float2bfloat16_rn(v11); Ch[i01 + 8] = h; Cl[i01 + 8] = __float2bfloat16_rn(v11 - __bfloat162float(h));
            }
        }
    } else {
        #pragma unroll
        for (int nf = 0; nf < 4; nf++) {
            const int col = n0 + warp_n * 32 + nf * 8 + t * 2;
            float b0 = 0.f, b1 = 0.f;
            if (MODE == MODE_BIAS_F32 || MODE == MODE_BIAS_SPLIT) {
                b0 = aux[col]; b1 = aux[col + 1];
            }
            #pragma unroll
            for (int mf = 0; mf < 4; mf++) {
                const int row0 = m0 + warp_m * 64 + mf * 16 + g;
                float r00 = b0, r01 = b1, r10 = b0, r11 = b1;
                if (MODE == MODE_RES_SPLIT) {
                    float2 rr0 = *(const float2*)(R + (long)row0 * N + col);
                    float2 rr1 = *(const float2*)(R + (long)(row0 + 8) * N + col);
                    r00 = rr0.x; r01 = rr0.y; r10 = rr1.x; r11 = rr1.y;
                }
                const float v00 = acc[mf][nf][0] + r00;
                const float v01 = acc[mf][nf][1] + r01;
                const float v10 = acc[mf][nf][2] + r10;
                const float v11 = acc[mf][nf][3] + r11;
                if (MODE == MODE_BIAS_F32 || MODE == MODE_PLAIN_F32) {
                    *(float2*)(C + (long)row0 * N + col)       = make_float2(v00, v01);
                    *(float2*)(C + (long)(row0 + 8) * N + col) = make_float2(v10, v11);
                } else {
                    uint32_t h0, l0, h1, l1;
                    split2(v00, v01, h0, l0);
                    split2(v10, v11, h1, l1);
                    *(uint32_t*)(Ch + (long)row0 * N + col)       = h0;
                    *(uint32_t*)(Cl + (long)row0 * N + col)       = l0;
                    *(uint32_t*)(Ch + (long)(row0 + 8) * N + col) = h1;
                    *(uint32_t*)(Cl + (long)(row0 + 8) * N + col) = l1;
                }
            }
        }
    }
}

// ============================================================
// Row softmax over SS=4096 columns -> bf16 hi/lo output.
// One block (256 thr) per row.
// ============================================================
__global__ __launch_bounds__(256)
void softmax_split(const float* __restrict__ attn,
                   bf16* __restrict__ ph, bf16* __restrict__ pl)
{
    const size_t rb = (size_t)blockIdx.x * SS;
    const float* p = attn + rb;
    const int tid = threadIdx.x;

    float4 v[4];
    float mx = -INFINITY;
    #pragma unroll
    for (int i = 0; i < 4; i++) {
        v[i] = *(const float4*)(p + (tid + i * 256) * 4);
        mx = fmaxf(fmaxf(fmaxf(v[i].x, v[i].y), fmaxf(v[i].z, v[i].w)), mx);
    }
    __shared__ float red[8];
    #pragma unroll
    for (int o = 16; o; o >>= 1) mx = fmaxf(mx, __shfl_xor_sync(0xffffffffu, mx, o));
    if ((tid & 31) == 0) red[tid >> 5] = mx;
    __syncthreads();
    float m = red[0];
    #pragma unroll
    for (int i = 1; i < 8; i++) m = fmaxf(m, red[i]);
    __syncthreads();

    float s = 0.f;
    #pragma unroll
    for (int i = 0; i < 4; i++) {
        v[i].x = __expf(v[i].x - m); v[i].y = __expf(v[i].y - m);
        v[i].z = __expf(v[i].z - m); v[i].w = __expf(v[i].w - m);
        s += v[i].x + v[i].y + v[i].z + v[i].w;
    }
    #pragma unroll
    for (int o = 16; o; o >>= 1) s += __shfl_xor_sync(0xffffffffu, s, o);
    if ((tid & 31) == 0) red[tid >> 5] = s;
    __syncthreads();
    float tot = 0.f;
    #pragma unroll
    for (int i = 0; i < 8; i++) tot += red[i];
    const float inv = 1.f / tot;

    #pragma unroll
    for (int i = 0; i < 4; i++) {
        const float p0 = v[i].x * inv, p1 = v[i].y * inv;
        const float p2 = v[i].z * inv, p3 = v[i].w * inv;
        uint32_t h0, l0, h1, l1;
        split2(p0, p1, h0, l0);
        split2(p2, p3, h1, l1);
        const size_t idx = rb + (size_t)(tid + i * 256) * 4;
        *(uint2*)(ph + idx) = make_uint2(h0, h1);
        *(uint2*)(pl + idx) = make_uint2(l0, l1);
    }
}

// ============================================================
extern "C" void kernel_launch(void* const* d_in, const int* in_sizes, int n_in,
                              void* d_out, int out_size)
{
    const float* x   = (const float*)d_in[0];
    const float* y   = (const float*)d_in[1];
    const float* Wq  = (const float*)d_in[2];
    const float* bq  = (const float*)d_in[3];
    const float* Wqv = (const float*)d_in[4];
    const float* bqv = (const float*)d_in[5];
    const float* Wk  = (const float*)d_in[6];
    const float* bk  = (const float*)d_in[7];
    const float* Wkv = (const float*)d_in[8];
    const float* bkv = (const float*)d_in[9];
    const float* Wf  = (const float*)d_in[10];
    const float* bf  = (const float*)d_in[11];
    float* out = (float*)d_out;

    bf16 *xs_h, *xs_l, *ys_h, *ys_l;
    bf16 *Wq_h, *Wq_l, *Wqv_h, *Wqv_l, *Wk_h, *Wk_l, *Wkv_h, *Wkv_l, *Wf_h, *Wf_l;
    bf16 *q_h, *q_l, *k_h, *k_l, *kvT_h, *kvT_l, *o_h, *o_l, *at_h, *at_l;
    float *qv, *attn;
    cudaGetSymbolAddress((void**)&xs_h,  g_xs_h);  cudaGetSymbolAddress((void**)&xs_l,  g_xs_l);
    cudaGetSymbolAddress((void**)&ys_h,  g_ys_h);  cudaGetSymbolAddress((void**)&ys_l,  g_ys_l);
    cudaGetSymbolAddress((void**)&Wq_h,  g_Wq_h);  cudaGetSymbolAddress((void**)&Wq_l,  g_Wq_l);
    cudaGetSymbolAddress((void**)&Wqv_h, g_Wqv_h); cudaGetSymbolAddress((void**)&Wqv_l, g_Wqv_l);
    cudaGetSymbolAddress((void**)&Wk_h,  g_Wk_h);  cudaGetSymbolAddress((void**)&Wk_l,  g_Wk_l);
    cudaGetSymbolAddress((void**)&Wkv_h, g_Wkv_h); cudaGetSymbolAddress((void**)&Wkv_l, g_Wkv_l);
    cudaGetSymbolAddress((void**)&Wf_h,  g_Wf_h);  cudaGetSymbolAddress((void**)&Wf_l,  g_Wf_l);
    cudaGetSymbolAddress((void**)&q_h,   g_q_h);   cudaGetSymbolAddress((void**)&q_l,   g_q_l);
    cudaGetSymbolAddress((void**)&k_h,   g_k_h);   cudaGetSymbolAddress((void**)&k_l,   g_k_l);
    cudaGetSymbolAddress((void**)&kvT_h, g_kvT_h); cudaGetSymbolAddress((void**)&kvT_l, g_kvT_l);
    cudaGetSymbolAddress((void**)&o_h,   g_o_h);   cudaGetSymbolAddress((void**)&o_l,   g_o_l);
    cudaGetSymbolAddress((void**)&at_h,  g_attn_h);cudaGetSymbolAddress((void**)&at_l,  g_attn_l);
    cudaGetSymbolAddress((void**)&qv,    g_qv);
    cudaGetSymbolAddress((void**)&attn,  g_attn);

    cudaFuncSetAttribute(cp_nt3<MODE_BIAS_F32>,    cudaFuncAttributeMaxDynamicSharedMemorySize, SMEM_BYTES);
    cudaFuncSetAttribute(cp_nt3<MODE_TBIAS_SPLIT>, cudaFuncAttributeMaxDynamicSharedMemorySize, SMEM_BYTES);
    cudaFuncSetAttribute(cp_nt3<MODE_PLAIN_F32>,   cudaFuncAttributeMaxDynamicSharedMemorySize, SMEM_BYTES);
    cudaFuncSetAttribute(cp_nt3<MODE_RES_SPLIT>,   cudaFuncAttributeMaxDynamicSharedMemorySize, SMEM_BYTES);
    cudaFuncSetAttribute(cp_nt3<MODE_BIAS_SPLIT>,  cudaFuncAttributeMaxDynamicSharedMemorySize, SMEM_BYTES);

    dim3 thr(NTHR);

    // 0. presplit inputs and weights to bf16 hi/lo
    presplit<<<MTOT * DD / 1024, 256>>>(x, xs_h, xs_l, MTOT * DD);
    presplit<<<MTOT * DD / 1024, 256>>>(y, ys_h, ys_l, MTOT * DD);
    presplit<<<DD * DD / 1024, 256>>>(Wq,  Wq_h,  Wq_l,  DD * DD);
    presplit<<<DD * DD / 1024, 256>>>(Wqv, Wqv_h, Wqv_l, DD * DD);
    presplit<<<DD * DD / 1024, 256>>>(Wk,  Wk_h,  Wk_l,  DD * DD);
    presplit<<<DD * DD / 1024, 256>>>(Wkv, Wkv_h, Wkv_l, DD * DD);
    presplit<<<DD * DD / 1024, 256>>>(Wf,  Wf_h,  Wf_l,  DD * DD);

    // 1-4. projections
    {
        dim3 grid(DD / BN, MTOT / BM, 1);
        cp_nt3<MODE_BIAS_SPLIT> <<<grid, thr, SMEM_BYTES>>>(xs_h, xs_l, Wq_h,  Wq_l,  bq,  nullptr, q_h, q_l,
                                                            MTOT, DD, DD, 0, 0, 0, 0);
        cp_nt3<MODE_BIAS_F32>   <<<grid, thr, SMEM_BYTES>>>(xs_h, xs_l, Wqv_h, Wqv_l, bqv, qv, nullptr, nullptr,
                                                            MTOT, DD, DD, 0, 0, 0, 0);
        cp_nt3<MODE_BIAS_SPLIT> <<<grid, thr, SMEM_BYTES>>>(ys_h, ys_l, Wk_h,  Wk_l,  bk,  nullptr, k_h, k_l,
                                                            MTOT, DD, DD, 0, 0, 0, 0);
        cp_nt3<MODE_TBIAS_SPLIT><<<grid, thr, SMEM_BYTES>>>(ys_h, ys_l, Wkv_h, Wkv_l, bkv, nullptr, kvT_h, kvT_l,
                                                            MTOT, DD, DD, 0, 0, 0, 0);
    }

    // 5. scores = q @ k^T per batch: [4096,4096], K=512
    {
        dim3 grid(SS / BN, SS / BM, BB);
        cp_nt3<MODE_PLAIN_F32><<<grid, thr, SMEM_BYTES>>>(q_h, q_l, k_h, k_l, nullptr, attn, nullptr, nullptr,
                                                          SS, SS, DD,
                                                          (long)SS * DD, (long)SS * DD, 0, (long)SS * SS);
    }

    // 6. softmax -> bf16 hi/lo probabilities
    softmax_split<<<BB * SS, 256>>>(attn, at_h, at_l);

    // 7. o = attn @ kvT^T + qv per batch: [4096,512], K=4096 (NT form)
    {
        dim3 grid(DD / BN, SS / BM, BB);
        cp_nt3<MODE_RES_SPLIT><<<grid, thr, SMEM_BYTES>>>(at_h, at_l, kvT_h, kvT_l, qv, nullptr, o_h, o_l,
                                                          SS, DD, SS,
                                                          (long)SS * SS, (long)DD * SS,
                                                          (long)SS * DD, (long)SS * DD);
    }

    // 8. final = o @ Wf^T + bf: [16384,512]
    {
        dim3 grid(DD / BN, MTOT / BM, 1);
        cp_nt3<MODE_BIAS_F32><<<grid, thr, SMEM_BYTES>>>(o_h, o_l, Wf_h, Wf_l, bf, out, nullptr, nullptr,
                                                         MTOT, DD, DD, 0, 0, 0, 0);
    }
}

// round 17
// speedup vs baseline: 1.0376x; 1.0008x over previous
#include <cuda_runtime.h>
#include <cuda_bf16.h>
#include <math.h>
#include <stdint.h>

// Problem constants
#define BB 4
#define SS 4096
#define DD 512
#define MTOT (BB*SS)          // 16384 flattened rows

// Tiling
#define BM 128
#define BN 128
#define BK 32
#define NTHR 256              // 8 warps: 2 (M) x 4 (N), warp tile 64x32
#define STAGES 3

// smem: unpadded bf16 tiles 128 rows x 32 cols = 64B/row, XOR-swizzled chunks
#define TILE_B   (128 * 64)       // 8192 bytes
#define STAGE_B  (4 * TILE_B)     // Ahi, Alo, Bhi, Blo = 32768
#define SMEM_BYTES (STAGES * STAGE_B)  // 98304

// swizzled byte offset of 16B chunk (row, c), c = k-chunk 0..3
#define SWZ(row, c) ((uint32_t)((row) * 64 + ((((c) ^ (((row) >> 1) & 3))) << 4)))

// epilogue modes
#define MODE_BIAS_F32    0   // C_f32 = acc + bias      (final output)
#define MODE_TBIAS_SPLIT 1   // Ch/Cl = acc + bias, transposed [D][S] store (kvT)
#define MODE_PLAIN_F32   2   // C_f32 = acc             (attn logits)
#define MODE_RES_SPLIT   3   // Ch/Cl = acc + R         (o = AV + qv)
#define MODE_BIAS_SPLIT  4   // Ch/Cl = acc + bias      (q, k)

typedef __nv_bfloat16 bf16;

// -------- scratch (device globals: allocation-free rule) --------
__device__ bf16  g_xs_h[MTOT * DD], g_xs_l[MTOT * DD];
__device__ bf16  g_ys_h[MTOT * DD], g_ys_l[MTOT * DD];
__device__ bf16  g_Wq_h [DD * DD], g_Wq_l [DD * DD];
__device__ bf16  g_Wqv_h[DD * DD], g_Wqv_l[DD * DD];
__device__ bf16  g_Wk_h [DD * DD], g_Wk_l [DD * DD];
__device__ bf16  g_Wkv_h[DD * DD], g_Wkv_l[DD * DD];
__device__ bf16  g_Wf_h [DD * DD], g_Wf_l [DD * DD];
__device__ bf16  g_q_h [MTOT * DD], g_q_l [MTOT * DD];
__device__ bf16  g_k_h [MTOT * DD], g_k_l [MTOT * DD];
__device__ bf16  g_kvT_h[MTOT * DD], g_kvT_l[MTOT * DD];   // [B][D][S]
__device__ bf16  g_o_h [MTOT * DD], g_o_l [MTOT * DD];
__device__ float g_qv [MTOT * DD];
__device__ float g_attn[(size_t)BB * SS * SS];             // 256 MB logits
__device__ bf16  g_attn_h[(size_t)BB * SS * SS];           // 128 MB
__device__ bf16  g_attn_l[(size_t)BB * SS * SS];           // 128 MB

__device__ __forceinline__ uint32_t smem_u32(const void* p) {
    uint32_t a;
    asm("{ .reg .u64 t; cvta.to.shared.u64 t, %1; cvt.u32.u64 %0, t; }"
        : "=r"(a) : "l"(p));
    return a;
}

__device__ __forceinline__ void mma_bf16(float c[4],
                                         uint32_t a0, uint32_t a1, uint32_t a2, uint32_t a3,
                                         uint32_t b0, uint32_t b1) {
    asm volatile(
        "mma.sync.aligned.m16n8k16.row.col.f32.bf16.bf16.f32 "
        "{%0,%1,%2,%3}, {%4,%5,%6,%7}, {%8,%9}, {%0,%1,%2,%3};\n"
        : "+f"(c[0]), "+f"(c[1]), "+f"(c[2]), "+f"(c[3])
        : "r"(a0), "r"(a1), "r"(a2), "r"(a3), "r"(b0), "r"(b1));
}

__device__ __forceinline__ void ldsm4(uint32_t& r0, uint32_t& r1, uint32_t& r2, uint32_t& r3,
                                      uint32_t addr) {
    asm volatile("ldmatrix.sync.aligned.m8n8.x4.shared.b16 {%0,%1,%2,%3}, [%4];"
                 : "=r"(r0), "=r"(r1), "=r"(r2), "=r"(r3) : "r"(addr));
}

#define CP16(sp, gp) \
    asm volatile("cp.async.cg.shared.global [%0], [%1], 16;" :: "r"(sp), "l"(gp))
#define CP_COMMIT() asm volatile("cp.async.commit_group;" ::: "memory")
#define CP_WAIT1()  asm volatile("cp.async.wait_group 1;" ::: "memory")

// split float pair -> hi bf162 word + lo bf162 word
__device__ __forceinline__ void split2(float a, float b, uint32_t& h, uint32_t& l) {
    __nv_bfloat162 hh, ll;
    hh.x = __float2bfloat16_rn(a);
    hh.y = __float2bfloat16_rn(b);
    ll.x = __float2bfloat16_rn(a - __bfloat162float(hh.x));
    ll.y = __float2bfloat16_rn(b - __bfloat162float(hh.y));
    h = *(uint32_t*)&hh;
    l = *(uint32_t*)&ll;
}

// ============================================================
// presplit: fp32 -> bf16 hi + bf16 lo, elementwise
// ============================================================
__global__ __launch_bounds__(256)
void presplit(const float* __restrict__ in, bf16* __restrict__ hi,
              bf16* __restrict__ lo, int n)
{
    const int i = (blockIdx.x * 256 + threadIdx.x) * 4;
    if (i >= n) return;
    float4 v = *(const float4*)(in + i);
    uint32_t h0, l0, h1, l1;
    split2(v.x, v.y, h0, l0);
    split2(v.z, v.w, h1, l1);
    uint2 hh = make_uint2(h0, h1), ll = make_uint2(l0, l1);
    *(uint2*)(hi + i) = hh;
    *(uint2*)(lo + i) = ll;
}

// ============================================================
// NT bf16x3 GEMM, cp.async pipeline (1 barrier/k-tile),
// term-major mma ordering. C[M,N] = A[M,K] * B[N,K]^T.
// Batched via blockIdx.z. M,N %128==0, K %32==0.
// ============================================================
template <int MODE>
__global__ __launch_bounds__(NTHR, 2)
void cp_nt3(const bf16* __restrict__ Ah, const bf16* __restrict__ Al,
            const bf16* __restrict__ Bh, const bf16* __restrict__ Bl,
            const float* __restrict__ aux,      // bias or residual R
            float* __restrict__ C, bf16* __restrict__ Ch, bf16* __restrict__ Cl,
            int M, int N, int K,
            long sA, long sB, long sAux, long sC)
{
    extern __shared__ __align__(128) char smem[];
    const uint32_t sbase = smem_u32(smem);

    const int bz = blockIdx.z;
    Ah += (long)bz * sA;  Al += (long)bz * sA;
    Bh += (long)bz * sB;  Bl += (long)bz * sB;
    const float* R = aux ? aux + (long)bz * sAux : (const float*)0;
    if (C)  C  += (long)bz * sC;
    if (Ch) { Ch += (long)bz * sC; Cl += (long)bz * sC; }

    const int m0 = blockIdx.y * BM;
    const int n0 = blockIdx.x * BN;
    const int tid  = threadIdx.x;
    const int wid  = tid >> 5;
    const int lane = tid & 31;
    const int g = lane >> 2;       // 0..7
    const int t = lane & 3;        // 0..3
    const int warp_m = wid & 1;    // 0..1
    const int warp_n = wid >> 1;   // 0..3

    // ldmatrix lane roles
    const int quad = lane >> 3;
    const int lr8  = lane & 7;
    const int rq   = (quad & 1) * 8 + lr8;
    const int cq   = quad >> 1;

    // loader roles: j 0..7 -> tile j>>1, row (tid>>2)+64*(j&1), chunk tid&3
    const int lrow  = tid >> 2;
    const int lchnk = tid & 3;
    const bf16* tb[4] = { Ah + (long)m0 * K, Al + (long)m0 * K,
                          Bh + (long)n0 * K, Bl + (long)n0 * K };

    float acc[4][4][4];
    #pragma unroll
    for (int mf = 0; mf < 4; mf++)
        #pragma unroll
        for (int nf = 0; nf < 4; nf++)
            #pragma unroll
            for (int r = 0; r < 4; r++) acc[mf][nf][r] = 0.f;

    const int KT = K / BK;

    #define ISSUE_STAGE(kt_, s_) do {                                          \
        const int k0_ = (kt_) * BK;                                            \
        _Pragma("unroll")                                                      \
        for (int j = 0; j < 8; j++) {                                          \
            const int tile_ = j >> 1;                                          \
            const int row_  = lrow + 64 * (j & 1);                             \
            const bf16* gp_ = tb[tile_] + (long)row_ * K + k0_ + lchnk * 8;    \
            uint32_t sp_ = sbase + (s_) * STAGE_B + tile_ * TILE_B             \
                         + SWZ(row_, lchnk);                                   \
            CP16(sp_, gp_);                                                    \
        }                                                                      \
    } while (0)

    ISSUE_STAGE(0, 0); CP_COMMIT();
    ISSUE_STAGE(1, 1); CP_COMMIT();

    for (int kt = 0; kt < KT; kt++) {
        // ensure stage kt%3 complete (<=1 newer group in flight)
        CP_WAIT1();
        __syncthreads();   // all warps see stage kt AND finished iter kt-1 reads

        // writing stage (kt+2)%3 == (kt-1)%3 is WAR-safe after the barrier
        if (kt + 2 < KT) ISSUE_STAGE(kt + 2, (kt + 2) % STAGES);
        CP_COMMIT();       // always commit (empty group on tail keeps count)

        const uint32_t stg = sbase + (kt % STAGES) * STAGE_B;
        const uint32_t aHiB = stg;
        const uint32_t aLoB = stg + TILE_B;
        const uint32_t bHiB = stg + 2 * TILE_B;
        const uint32_t bLoB = stg + 3 * TILE_B;

        #pragma unroll
        for (int ks = 0; ks < 2; ks++) {
            const int ck = ks * 2 + cq;
            uint32_t ah[4][4], al[4][4], bh[4][2], bl[4][2];
            #pragma unroll
            for (int mf = 0; mf < 4; mf++) {
                const int row = warp_m * 64 + mf * 16 + rq;
                const uint32_t off = SWZ(row, ck);
                ldsm4(ah[mf][0], ah[mf][1], ah[mf][2], ah[mf][3], aHiB + off);
                ldsm4(al[mf][0], al[mf][1], al[mf][2], al[mf][3], aLoB + off);
            }
            #pragma unroll
            for (int p = 0; p < 2; p++) {
                const int row = warp_n * 32 + p * 16 + rq;
                const uint32_t off = SWZ(row, ck);
                uint32_t q0, q1, q2, q3;
                ldsm4(q0, q1, q2, q3, bHiB + off);
                bh[2*p][0] = q0; bh[2*p+1][0] = q1;
                bh[2*p][1] = q2; bh[2*p+1][1] = q3;
                ldsm4(q0, q1, q2, q3, bLoB + off);
                bl[2*p][0] = q0; bl[2*p+1][0] = q1;
                bl[2*p][1] = q2; bl[2*p+1][1] = q3;
            }
            // term-major ordering: same-acc mmas spaced apart
            #pragma unroll
            for (int mf = 0; mf < 4; mf++)
                #pragma unroll
                for (int nf = 0; nf < 4; nf++)
                    mma_bf16(acc[mf][nf], ah[mf][0], ah[mf][1], ah[mf][2], ah[mf][3],
                             bh[nf][0], bh[nf][1]);
            #pragma unroll
            for (int mf = 0; mf < 4; mf++)
                #pragma unroll
                for (int nf = 0; nf < 4; nf++)
                    mma_bf16(acc[mf][nf], ah[mf][0], ah[mf][1], ah[mf][2], ah[mf][3],
                             bl[nf][0], bl[nf][1]);
            #pragma unroll
            for (int mf = 0; mf < 4; mf++)
                #pragma unroll
                for (int nf = 0; nf < 4; nf++)
                    mma_bf16(acc[mf][nf], al[mf][0], al[mf][1], al[mf][2], al[mf][3],
                             bh[nf][0], bh[nf][1]);
        }
    }

    // ---------------- epilogue ----------------
    if (MODE == MODE_TBIAS_SPLIT) {
        const long cbase = (long)(m0 >> 12) * DD * SS;
        const int  s0    = (m0 & (SS - 1)) + warp_m * 64;
        #pragma unroll
        for (int nf = 0; nf < 4; nf++) {
            const int col = warp_n * 32 + nf * 8 + t * 2;
            const float b0 = aux[n0 + col];
            const float b1 = aux[n0 + col + 1];
            #pragma unroll
            for (int mf = 0; mf < 4; mf++) {
                const int srow = s0 + mf * 16 + g;
                const long i00 = cbase + (long)(n0 + col) * SS + srow;
                const long i01 = cbase + (long)(n0 + col + 1) * SS + srow;
                float v00 = acc[mf][nf][0] + b0, v01 = acc[mf][nf][1] + b1;
                float v10 = acc[mf][nf][2] + b0, v11 = acc[mf][nf][3] + b1;
                bf16 h;
                h = __float2bfloat16_rn(v00); Ch[i00]     = h; Cl[i00]     = __float2bfloat16_rn(v00 - __bfloat162float(h));
                h = __float2bfloat16_rn(v01); Ch[i01]     = h; Cl[i01]     = __float2bfloat16_rn(v01 - __bfloat162float(h));
                h = __float2bfloat16_rn(v10); Ch[i00 + 8] = h; Cl[i00 + 8] = __float2bfloat16_rn(v10 - __bfloat162float(h));
                h = __float2bfloat16_rn(v11); Ch[i01 + 8] = h; Cl[i01 + 8] = __float2bfloat16_rn(v11 - __bfloat162float(h));
            }
        }
    } else {
        #pragma unroll
        for (int nf = 0; nf < 4; nf++) {
            const int col = n0 + warp_n * 32 + nf * 8 + t * 2;
            float b0 = 0.f, b1 = 0.f;
            if (MODE == MODE_BIAS_F32 || MODE == MODE_BIAS_SPLIT) {
                b0 = aux[col]; b1 = aux[col + 1];
            }
            #pragma unroll
            for (int mf = 0; mf < 4; mf++) {
                const int row0 = m0 + warp_m * 64 + mf * 16 + g;
                float r00 = b0, r01 = b1, r10 = b0, r11 = b1;
                if (MODE == MODE_RES_SPLIT) {
                    float2 rr0 = *(const float2*)(R + (long)row0 * N + col);
                    float2 rr1 = *(const float2*)(R + (long)(row0 + 8) * N + col);
                    r00 = rr0.x; r01 = rr0.y; r10 = rr1.x; r11 = rr1.y;
                }
                const float v00 = acc[mf][nf][0] + r00;
                const float v01 = acc[mf][nf][1] + r01;
                const float v10 = acc[mf][nf][2] + r10;
                const float v11 = acc[mf][nf][3] + r11;
                if (MODE == MODE_BIAS_F32 || MODE == MODE_PLAIN_F32) {
                    *(float2*)(C + (long)row0 * N + col)       = make_float2(v00, v01);
                    *(float2*)(C + (long)(row0 + 8) * N + col) = make_float2(v10, v11);
                } else {
                    uint32_t h0, l0, h1, l1;
                    split2(v00, v01, h0, l0);
                    split2(v10, v11, h1, l1);
                    *(uint32_t*)(Ch + (long)row0 * N + col)       = h0;
                    *(uint32_t*)(Cl + (long)row0 * N + col)       = l0;
                    *(uint32_t*)(Ch + (long)(row0 + 8) * N + col) = h1;
                    *(uint32_t*)(Cl + (long)(row0 + 8) * N + col) = l1;
                }
            }
        }
    }
}

// ============================================================
// Row softmax over SS=4096 columns -> bf16 hi/lo output.
// One block (256 thr) per row.
// ============================================================
__global__ __launch_bounds__(256)
void softmax_split(const float* __restrict__ attn,
                   bf16* __restrict__ ph, bf16* __restrict__ pl)
{
    const size_t rb = (size_t)blockIdx.x * SS;
    const float* p = attn + rb;
    const int tid = threadIdx.x;

    float4 v[4];
    float mx = -INFINITY;
    #pragma unroll
    for (int i = 0; i < 4; i++) {
        v[i] = *(const float4*)(p + (tid + i * 256) * 4);
        mx = fmaxf(fmaxf(fmaxf(v[i].x, v[i].y), fmaxf(v[i].z, v[i].w)), mx);
    }
    __shared__ float red[8];
    #pragma unroll
    for (int o = 16; o; o >>= 1) mx = fmaxf(mx, __shfl_xor_sync(0xffffffffu, mx, o));
    if ((tid & 31) == 0) red[tid >> 5] = mx;
    __syncthreads();
    float m = red[0];
    #pragma unroll
    for (int i = 1; i < 8; i++) m = fmaxf(m, red[i]);
    __syncthreads();

    float s = 0.f;
    #pragma unroll
    for (int i = 0; i < 4; i++) {
        v[i].x = __expf(v[i].x - m); v[i].y = __expf(v[i].y - m);
        v[i].z = __expf(v[i].z - m); v[i].w = __expf(v[i].w - m);
        s += v[i].x + v[i].y + v[i].z + v[i].w;
    }
    #pragma unroll
    for (int o = 16; o; o >>= 1) s += __shfl_xor_sync(0xffffffffu, s, o);
    if ((tid & 31) == 0) red[tid >> 5] = s;
    __syncthreads();
    float tot = 0.f;
    #pragma unroll
    for (int i = 0; i < 8; i++) tot += red[i];
    const float inv = 1.f / tot;

    #pragma unroll
    for (int i = 0; i < 4; i++) {
        const float p0 = v[i].x * inv, p1 = v[i].y * inv;
        const float p2 = v[i].z * inv, p3 = v[i].w * inv;
        uint32_t h0, l0, h1, l1;
        split2(p0, p1, h0, l0);
        split2(p2, p3, h1, l1);
        const size_t idx = rb + (size_t)(tid + i * 256) * 4;
        *(uint2*)(ph + idx) = make_uint2(h0, h1);
        *(uint2*)(pl + idx) = make_uint2(l0, l1);
    }
}

// ============================================================
extern "C" void kernel_launch(void* const* d_in, const int* in_sizes, int n_in,
                              void* d_out, int out_size)
{
    const float* x   = (const float*)d_in[0];
    const float* y   = (const float*)d_in[1];
    const float* Wq  = (const float*)d_in[2];
    const float* bq  = (const float*)d_in[3];
    const float* Wqv = (const float*)d_in[4];
    const float* bqv = (const float*)d_in[5];
    const float* Wk  = (const float*)d_in[6];
    const float* bk  = (const float*)d_in[7];
    const float* Wkv = (const float*)d_in[8];
    const float* bkv = (const float*)d_in[9];
    const float* Wf  = (const float*)d_in[10];
    const float* bf  = (const float*)d_in[11];
    float* out = (float*)d_out;

    bf16 *xs_h, *xs_l, *ys_h, *ys_l;
    bf16 *Wq_h, *Wq_l, *Wqv_h, *Wqv_l, *Wk_h, *Wk_l, *Wkv_h, *Wkv_l, *Wf_h, *Wf_l;
    bf16 *q_h, *q_l, *k_h, *k_l, *kvT_h, *kvT_l, *o_h, *o_l, *at_h, *at_l;
    float *qv, *attn;
    cudaGetSymbolAddress((void**)&xs_h,  g_xs_h);  cudaGetSymbolAddress((void**)&xs_l,  g_xs_l);
    cudaGetSymbolAddress((void**)&ys_h,  g_ys_h);  cudaGetSymbolAddress((void**)&ys_l,  g_ys_l);
    cudaGetSymbolAddress((void**)&Wq_h,  g_Wq_h);  cudaGetSymbolAddress((void**)&Wq_l,  g_Wq_l);
    cudaGetSymbolAddress((void**)&Wqv_h, g_Wqv_h); cudaGetSymbolAddress((void**)&Wqv_l, g_Wqv_l);
    cudaGetSymbolAddress((void**)&Wk_h,  g_Wk_h);  cudaGetSymbolAddress((void**)&Wk_l,  g_Wk_l);
    cudaGetSymbolAddress((void**)&Wkv_h, g_Wkv_h); cudaGetSymbolAddress((void**)&Wkv_l, g_Wkv_l);
    cudaGetSymbolAddress((void**)&Wf_h,  g_Wf_h);  cudaGetSymbolAddress((void**)&Wf_l,  g_Wf_l);
    cudaGetSymbolAddress((void**)&q_h,   g_q_h);   cudaGetSymbolAddress((void**)&q_l,   g_q_l);
    cudaGetSymbolAddress((void**)&k_h,   g_k_h);   cudaGetSymbolAddress((void**)&k_l,   g_k_l);
    cudaGetSymbolAddress((void**)&kvT_h, g_kvT_h); cudaGetSymbolAddress((void**)&kvT_l, g_kvT_l);
    cudaGetSymbolAddress((void**)&o_h,   g_o_h);   cudaGetSymbolAddress((void**)&o_l,   g_o_l);
    cudaGetSymbolAddress((void**)&at_h,  g_attn_h);cudaGetSymbolAddress((void**)&at_l,  g_attn_l);
    cudaGetSymbolAddress((void**)&qv,    g_qv);
    cudaGetSymbolAddress((void**)&attn,  g_attn);

    cudaFuncSetAttribute(cp_nt3<MODE_BIAS_F32>,    cudaFuncAttributeMaxDynamicSharedMemorySize, SMEM_BYTES);
    cudaFuncSetAttribute(cp_nt3<MODE_TBIAS_SPLIT>, cudaFuncAttributeMaxDynamicSharedMemorySize, SMEM_BYTES);
    cudaFuncSetAttribute(cp_nt3<MODE_PLAIN_F32>,   cudaFuncAttributeMaxDynamicSharedMemorySize, SMEM_BYTES);
    cudaFuncSetAttribute(cp_nt3<MODE_RES_SPLIT>,   cudaFuncAttributeMaxDynamicSharedMemorySize, SMEM_BYTES);
    cudaFuncSetAttribute(cp_nt3<MODE_BIAS_SPLIT>,  cudaFuncAttributeMaxDynamicSharedMemorySize, SMEM_BYTES);

    dim3 thr(NTHR);
    dim3 gproj(DD / BN, MTOT / BM, 1);

    // Launch order arranged so ncu (-s 5 -c 1) captures launch #6 = q-projection GEMM.
    presplit<<<MTOT * DD / 1024, 256>>>(x, xs_h, xs_l, MTOT * DD);   // 1
    presplit<<<MTOT * DD / 1024, 256>>>(y, ys_h, ys_l, MTOT * DD);   // 2
    presplit<<<DD * DD / 1024, 256>>>(Wq,  Wq_h,  Wq_l,  DD * DD);   // 3
    presplit<<<DD * DD / 1024, 256>>>(Wk,  Wk_h,  Wk_l,  DD * DD);   // 4
    presplit<<<DD * DD / 1024, 256>>>(Wqv, Wqv_h, Wqv_l, DD * DD);   // 5

    // 6: projection q (captured by ncu)
    cp_nt3<MODE_BIAS_SPLIT> <<<gproj, thr, SMEM_BYTES>>>(xs_h, xs_l, Wq_h, Wq_l, bq,
                                                         nullptr, q_h, q_l,
                                                         MTOT, DD, DD, 0, 0, 0, 0);
    // 7: projection k
    cp_nt3<MODE_BIAS_SPLIT> <<<gproj, thr, SMEM_BYTES>>>(ys_h, ys_l, Wk_h, Wk_l, bk,
                                                         nullptr, k_h, k_l,
                                                         MTOT, DD, DD, 0, 0, 0, 0);
    // remaining presplits
    presplit<<<DD * DD / 1024, 256>>>(Wkv, Wkv_h, Wkv_l, DD * DD);
    presplit<<<DD * DD / 1024, 256>>>(Wf,  Wf_h,  Wf_l,  DD * DD);

    // remaining projections
    cp_nt3<MODE_BIAS_F32>   <<<gproj, thr, SMEM_BYTES>>>(xs_h, xs_l, Wqv_h, Wqv_l, bqv,
                                                         qv, nullptr, nullptr,
                                                         MTOT, DD, DD, 0, 0, 0, 0);
    cp_nt3<MODE_TBIAS_SPLIT><<<gproj, thr, SMEM_BYTES>>>(ys_h, ys_l, Wkv_h, Wkv_l, bkv,
                                                         nullptr, kvT_h, kvT_l,
                                                         MTOT, DD, DD, 0, 0, 0, 0);

    // scores = q @ k^T per batch: [4096,4096], K=512 — full 3-term
    {
        dim3 grid(SS / BN, SS / BM, BB);
        cp_nt3<MODE_PLAIN_F32><<<grid, thr, SMEM_BYTES>>>(q_h, q_l, k_h, k_l, nullptr,
                                                          attn, nullptr, nullptr,
                                                          SS, SS, DD,
                                                          (long)SS * DD, (long)SS * DD, 0, (long)SS * SS);
    }

    // softmax -> bf16 hi/lo probabilities
    softmax_split<<<BB * SS, 256>>>(attn, at_h, at_l);

    // o = attn @ kvT^T + qv per batch: [4096,512], K=4096 (NT form) — full 3-term
    {
        dim3 grid(DD / BN, SS / BM, BB);
        cp_nt3<MODE_RES_SPLIT><<<grid, thr, SMEM_BYTES>>>(at_h, at_l, kvT_h, kvT_l, qv,
                                                          nullptr, o_h, o_l,
                                                          SS, DD, SS,
                                                          (long)SS * SS, (long)DD * SS,
                                                          (long)SS * DD, (long)SS * DD);
    }

    // final = o @ Wf^T + bf: [16384,512]
    cp_nt3<MODE_BIAS_F32><<<gproj, thr, SMEM_BYTES>>>(o_h, o_l, Wf_h, Wf_l, bf,
                                                      out, nullptr, nullptr,
                                                      MTOT, DD, DD, 0, 0, 0, 0);
}